// round 8
// baseline (speedup 1.0000x reference)
#include <cuda_runtime.h>
#include <math.h>
#include <stdint.h>

// Shapes (fixed for this problem)
#define BB  1024   // batch
#define PP  256    // patches
#define DD  1024   // dino dim
#define DC  512    // clip dim

// Scratch (no allocation allowed)
__device__ float g_tn[BB * DD];   // normalized t
__device__ float g_t [BB * DD];   // tanh(text @ W^T + b)
__device__ float g_vb[BB * DD];   // normalized best patch per batch

__device__ __forceinline__ uint32_t f2tf32(float f) {
    uint32_t u;
    asm("cvt.rna.tf32.f32 %0, %1;" : "=r"(u) : "f"(f));
    return u;
}

#define MMA_TF32(acc, a, b) \
    asm volatile( \
        "mma.sync.aligned.m16n8k8.row.col.f32.tf32.tf32.f32 " \
        "{%0,%1,%2,%3}, {%4,%5,%6,%7}, {%8,%9}, {%0,%1,%2,%3};" \
        : "+f"((acc)[0]), "+f"((acc)[1]), "+f"((acc)[2]), "+f"((acc)[3]) \
        : "r"((a)[0]), "r"((a)[1]), "r"((a)[2]), "r"((a)[3]), \
          "r"((b)[0]), "r"((b)[1]))

// ===========================================================================
// Split-tf32 GEMM1 (argmax-critical, fp32-equivalent): single-buffered.
// C[m,n] = tanh( sum_k A[m,k]*B[n,k] + bias[n] )
// BM=BN=64, BK=32, 128 threads, 2x2 warps, 32x32 warp tile.
// ===========================================================================
template<int K>
__global__ void __launch_bounds__(128)
gemm_split_tanh(const float* __restrict__ A, const float* __restrict__ Bm,
                const float* __restrict__ bias, float* __restrict__ C)
{
    constexpr int PITCH = 68;            // hi at [0,32), lo at [32,64)
    constexpr int NKT   = K / 32;

    __shared__ uint32_t As[64][PITCH];
    __shared__ uint32_t Bs[64][PITCH];

    const int tid  = threadIdx.x;
    const int lane = tid & 31;
    const int warp = tid >> 5;
    const int wm   = warp >> 1;
    const int wn   = warp & 1;
    const int gid  = lane >> 2;
    const int tig  = lane & 3;

    const int m0 = blockIdx.y * 64;
    const int n0 = blockIdx.x * 64;

    const int lr = tid >> 3;
    const int lc = tid & 7;

    float c[2][4][4];
    #pragma unroll
    for (int i = 0; i < 2; i++)
        #pragma unroll
        for (int j = 0; j < 4; j++)
            #pragma unroll
            for (int q = 0; q < 4; q++) c[i][j][q] = 0.f;

    float4 pa[4], pb[4];

    auto load_tile = [&](int kk) {
        #pragma unroll
        for (int i = 0; i < 4; i++) {
            const int r = lr + i * 16;
            pa[i] = *(const float4*)(A  + (size_t)(m0 + r) * K + kk + lc * 4);
            pb[i] = *(const float4*)(Bm + (size_t)(n0 + r) * K + kk + lc * 4);
        }
    };
    auto store_tile = [&]() {
        #pragma unroll
        for (int i = 0; i < 4; i++) {
            const int r = lr + i * 16;
            uint4 ah = make_uint4(f2tf32(pa[i].x), f2tf32(pa[i].y),
                                  f2tf32(pa[i].z), f2tf32(pa[i].w));
            uint4 bh = make_uint4(f2tf32(pb[i].x), f2tf32(pb[i].y),
                                  f2tf32(pb[i].z), f2tf32(pb[i].w));
            uint4 al = make_uint4(f2tf32(pa[i].x - __uint_as_float(ah.x)),
                                  f2tf32(pa[i].y - __uint_as_float(ah.y)),
                                  f2tf32(pa[i].z - __uint_as_float(ah.z)),
                                  f2tf32(pa[i].w - __uint_as_float(ah.w)));
            uint4 bl = make_uint4(f2tf32(pb[i].x - __uint_as_float(bh.x)),
                                  f2tf32(pb[i].y - __uint_as_float(bh.y)),
                                  f2tf32(pb[i].z - __uint_as_float(bh.z)),
                                  f2tf32(pb[i].w - __uint_as_float(bh.w)));
            *(uint4*)&As[r][lc * 4]      = ah;
            *(uint4*)&As[r][32 + lc * 4] = al;
            *(uint4*)&Bs[r][lc * 4]      = bh;
            *(uint4*)&Bs[r][32 + lc * 4] = bl;
        }
    };

    load_tile(0);
    store_tile();
    __syncthreads();

    for (int kt = 0; kt < NKT; kt++) {
        if (kt + 1 < NKT) load_tile((kt + 1) * 32);

        #pragma unroll
        for (int k8 = 0; k8 < 4; k8++) {
            const int k0 = k8 * 8;

            uint32_t af[2][4], afl[2][4];
            #pragma unroll
            for (int mi = 0; mi < 2; mi++) {
                const int row = wm * 32 + mi * 16 + gid;
                af[mi][0]  = As[row    ][k0 + tig];
                af[mi][1]  = As[row + 8][k0 + tig];
                af[mi][2]  = As[row    ][k0 + tig + 4];
                af[mi][3]  = As[row + 8][k0 + tig + 4];
                afl[mi][0] = As[row    ][32 + k0 + tig];
                afl[mi][1] = As[row + 8][32 + k0 + tig];
                afl[mi][2] = As[row    ][32 + k0 + tig + 4];
                afl[mi][3] = As[row + 8][32 + k0 + tig + 4];
            }
            uint32_t bf[4][2], bfl[4][2];
            #pragma unroll
            for (int nj = 0; nj < 4; nj++) {
                const int col = wn * 32 + nj * 8 + gid;
                bf[nj][0]  = Bs[col][k0 + tig];
                bf[nj][1]  = Bs[col][k0 + tig + 4];
                bfl[nj][0] = Bs[col][32 + k0 + tig];
                bfl[nj][1] = Bs[col][32 + k0 + tig + 4];
            }

            #pragma unroll
            for (int mi = 0; mi < 2; mi++)
                #pragma unroll
                for (int nj = 0; nj < 4; nj++) {
                    MMA_TF32(c[mi][nj], af[mi],  bf[nj]);    // hi*hi
                    MMA_TF32(c[mi][nj], af[mi],  bfl[nj]);   // hi*lo
                    MMA_TF32(c[mi][nj], afl[mi], bf[nj]);    // lo*hi
                }
        }

        if (kt + 1 < NKT) {
            __syncthreads();
            store_tile();
            __syncthreads();
        }
    }

    #pragma unroll
    for (int mi = 0; mi < 2; mi++) {
        const int row = m0 + wm * 32 + mi * 16 + gid;
        #pragma unroll
        for (int nj = 0; nj < 4; nj++) {
            const int col = n0 + wn * 32 + nj * 8 + tig * 2;
            const float b0 = bias[col], b1 = bias[col + 1];
            *(float2*)(C + (size_t)row * DD + col) =
                make_float2(tanhf(c[mi][nj][0] + b0), tanhf(c[mi][nj][1] + b1));
            *(float2*)(C + (size_t)(row + 8) * DD + col) =
                make_float2(tanhf(c[mi][nj][2] + b0), tanhf(c[mi][nj][3] + b1));
        }
    }
}

// ===========================================================================
// GEMM2: single-pass tf32, DOUBLE-BUFFERED smem (one sync per k-tile;
// stores of tile k+1 overlap MMAs of tile k). BM=BN=64, 128 threads.
// ===========================================================================
__global__ void __launch_bounds__(128)
gemm_db_tf32(const float* __restrict__ A, const float* __restrict__ Bm,
             float* __restrict__ C)
{
    constexpr int PITCH = 36;
    constexpr int NKT   = DD / 32;

    __shared__ uint32_t As[2][64][PITCH];
    __shared__ uint32_t Bs[2][64][PITCH];

    const int tid  = threadIdx.x;
    const int lane = tid & 31;
    const int warp = tid >> 5;
    const int wm   = warp >> 1;
    const int wn   = warp & 1;
    const int gid  = lane >> 2;
    const int tig  = lane & 3;

    const int m0 = blockIdx.y * 64;
    const int n0 = blockIdx.x * 64;

    const int lr = tid >> 3;
    const int lc = tid & 7;

    float c[2][4][4];
    #pragma unroll
    for (int i = 0; i < 2; i++)
        #pragma unroll
        for (int j = 0; j < 4; j++)
            #pragma unroll
            for (int q = 0; q < 4; q++) c[i][j][q] = 0.f;

    float4 pa[4], pb[4];

    auto load_tile = [&](int kk) {
        #pragma unroll
        for (int i = 0; i < 4; i++) {
            const int r = lr + i * 16;
            pa[i] = *(const float4*)(A  + (size_t)(m0 + r) * DD + kk + lc * 4);
            pb[i] = *(const float4*)(Bm + (size_t)(n0 + r) * DD + kk + lc * 4);
        }
    };
    auto store_tile = [&](int buf) {
        #pragma unroll
        for (int i = 0; i < 4; i++) {
            const int r = lr + i * 16;
            *(uint4*)&As[buf][r][lc * 4] = make_uint4(f2tf32(pa[i].x), f2tf32(pa[i].y),
                                                      f2tf32(pa[i].z), f2tf32(pa[i].w));
            *(uint4*)&Bs[buf][r][lc * 4] = make_uint4(f2tf32(pb[i].x), f2tf32(pb[i].y),
                                                      f2tf32(pb[i].z), f2tf32(pb[i].w));
        }
    };

    load_tile(0);
    store_tile(0);
    __syncthreads();

    for (int kt = 0; kt < NKT; kt++) {
        const int buf = kt & 1;
        if (kt + 1 < NKT) load_tile((kt + 1) * 32);

        #pragma unroll
        for (int k8 = 0; k8 < 4; k8++) {
            const int k0 = k8 * 8;

            uint32_t af[2][4];
            #pragma unroll
            for (int mi = 0; mi < 2; mi++) {
                const int row = wm * 32 + mi * 16 + gid;
                af[mi][0] = As[buf][row    ][k0 + tig];
                af[mi][1] = As[buf][row + 8][k0 + tig];
                af[mi][2] = As[buf][row    ][k0 + tig + 4];
                af[mi][3] = As[buf][row + 8][k0 + tig + 4];
            }
            uint32_t bf[4][2];
            #pragma unroll
            for (int nj = 0; nj < 4; nj++) {
                const int col = wn * 32 + nj * 8 + gid;
                bf[nj][0] = Bs[buf][col][k0 + tig];
                bf[nj][1] = Bs[buf][col][k0 + tig + 4];
            }

            #pragma unroll
            for (int mi = 0; mi < 2; mi++)
                #pragma unroll
                for (int nj = 0; nj < 4; nj++)
                    MMA_TF32(c[mi][nj], af[mi], bf[nj]);
        }

        // Write NEXT tile into the other buffer. Safe: the other buffer was
        // last READ in iteration kt-1, and the __syncthreads below (executed
        // at the end of every iteration) separates those reads from these
        // writes across warps.
        if (kt + 1 < NKT) store_tile(buf ^ 1);
        __syncthreads();
    }

    #pragma unroll
    for (int mi = 0; mi < 2; mi++) {
        const int row = m0 + wm * 32 + mi * 16 + gid;
        #pragma unroll
        for (int nj = 0; nj < 4; nj++) {
            const int col = n0 + wn * 32 + nj * 8 + tig * 2;
            *(float2*)(C + (size_t)row * DD + col) =
                make_float2(c[mi][nj][0], c[mi][nj][1]);
            *(float2*)(C + (size_t)(row + 8) * DD + col) =
                make_float2(c[mi][nj][2], c[mi][nj][3]);
        }
    }
}

// ---------------------------------------------------------------------------
// Row-wise L2 normalize
// ---------------------------------------------------------------------------
__global__ void __launch_bounds__(256)
norm_rows_kernel(const float* __restrict__ in, float* __restrict__ out)
{
    const int b = blockIdx.x;
    const int t = threadIdx.x;
    const int lane = t & 31, warp = t >> 5;
    const float4* i4 = (const float4*)(in + (size_t)b * DD);
    float4 v = i4[t];
    float ss = v.x*v.x + v.y*v.y + v.z*v.z + v.w*v.w;
    #pragma unroll
    for (int o = 16; o; o >>= 1) ss += __shfl_xor_sync(0xffffffffu, ss, o);

    __shared__ float sred[8];
    __shared__ float sinv;
    if (lane == 0) sred[warp] = ss;
    __syncthreads();
    if (t == 0) {
        float tot = 0.f;
        #pragma unroll
        for (int w = 0; w < 8; w++) tot += sred[w];
        sinv = 1.0f / fmaxf(sqrtf(tot), 1e-12f);
    }
    __syncthreads();
    const float inv = sinv;
    float4* o4 = (float4*)(out + (size_t)b * DD);
    v.x *= inv; v.y *= inv; v.z *= inv; v.w *= inv;
    o4[t] = v;
}

// ---------------------------------------------------------------------------
// sims + argmax + gather (HBM-bound; reads 1 GB once)
// ---------------------------------------------------------------------------
__global__ void __launch_bounds__(256)
sims_argmax_kernel(const float* __restrict__ visual,
                   const float* __restrict__ tn,
                   float* __restrict__ vb)
{
    const int b = blockIdx.x;
    const int lane = threadIdx.x & 31;
    const int warp = threadIdx.x >> 5;

    const float4* v4 = (const float4*)(visual + (size_t)b * PP * DD);
    const float4* t4 = (const float4*)(tn + (size_t)b * DD);

    float4 tr[8];
    #pragma unroll
    for (int k = 0; k < 8; k++) tr[k] = t4[lane + 32 * k];

    float best = -1e30f; int bidx = 0; float bss = 1.f;

    #pragma unroll 2
    for (int pp = 0; pp < 32; pp++) {
        const int p = warp * 32 + pp;
        const float4* row = v4 + (size_t)p * (DD / 4);
        float dot = 0.f, ss = 0.f;
        #pragma unroll
        for (int k = 0; k < 8; k++) {
            float4 v = row[lane + 32 * k];
            dot += v.x * tr[k].x + v.y * tr[k].y + v.z * tr[k].z + v.w * tr[k].w;
            ss  += v.x * v.x + v.y * v.y + v.z * v.z + v.w * v.w;
        }
        #pragma unroll
        for (int o = 16; o; o >>= 1) {
            dot += __shfl_xor_sync(0xffffffffu, dot, o);
            ss  += __shfl_xor_sync(0xffffffffu, ss,  o);
        }
        const float sim = dot / fmaxf(sqrtf(ss), 1e-12f);
        if (sim > best) { best = sim; bidx = p; bss = ss; }
    }

    __shared__ float sval[8]; __shared__ int sidx[8]; __shared__ float ssum[8];
    __shared__ int s_p; __shared__ float s_inv;
    if (lane == 0) { sval[warp] = best; sidx[warp] = bidx; ssum[warp] = bss; }
    __syncthreads();
    if (threadIdx.x == 0) {
        float bv = sval[0]; int bi = sidx[0]; float bs = ssum[0];
        #pragma unroll
        for (int w = 1; w < 8; w++) {
            if (sval[w] > bv || (sval[w] == bv && sidx[w] < bi)) {
                bv = sval[w]; bi = sidx[w]; bs = ssum[w];
            }
        }
        s_p = bi;
        s_inv = 1.0f / fmaxf(sqrtf(bs), 1e-12f);
    }
    __syncthreads();

    const int p = s_p;
    const float inv = s_inv;
    const float4* row = v4 + (size_t)p * (DD / 4);
    float4* ob = (float4*)(vb + (size_t)b * DD);
    for (int i = threadIdx.x; i < DD / 4; i += 256) {
        float4 v = row[i];
        v.x *= inv; v.y *= inv; v.z *= inv; v.w *= inv;
        ob[i] = v;
    }
}

// ---------------------------------------------------------------------------
extern "C" void kernel_launch(void* const* d_in, const int* in_sizes, int n_in,
                              void* d_out, int out_size)
{
    const float* visual = (const float*)d_in[0];   // [1024, 256, 1024]
    const float* text   = (const float*)d_in[1];   // [1024, 512]
    const float* W      = (const float*)d_in[2];   // [1024, 512]
    const float* bias   = (const float*)d_in[3];   // [1024]
    float* out = (float*)d_out;                    // [1024, 1024]

    float *p_t, *p_tn, *p_vb;
    cudaGetSymbolAddress((void**)&p_t,  g_t);
    cudaGetSymbolAddress((void**)&p_tn, g_tn);
    cudaGetSymbolAddress((void**)&p_vb, g_vb);

    // 1) t = tanh(text @ W^T + b)   (split-tf32: fp32-equivalent accuracy)
    gemm_split_tanh<DC><<<dim3(16, 16), 128>>>(text, W, bias, p_t);
    // 2) tn = l2norm(t)
    norm_rows_kernel<<<BB, 256>>>(p_t, p_tn);
    // 3) per-b argmax over patches + gather normalized best patch
    sims_argmax_kernel<<<BB, 256>>>(visual, p_tn, p_vb);
    // 4) out = tn @ vb^T  (single-pass tf32, double-buffered)
    gemm_db_tf32<<<dim3(16, 16), 128>>>(p_tn, p_vb, out);
}

// round 9
// speedup vs baseline: 1.0001x; 1.0001x over previous
#include <cuda_runtime.h>
#include <math.h>
#include <stdint.h>

// Shapes (fixed for this problem)
#define BB  1024   // batch
#define PP  256    // patches
#define DD  1024   // dino dim
#define DC  512    // clip dim

// Scratch (no allocation allowed)
__device__ float g_tn  [BB * DD];        // normalized t
__device__ float g_vb  [BB * DD];        // normalized best patch per batch
__device__ float g_part[2][BB * DD];     // split-K partial sums (reused)

__device__ __forceinline__ uint32_t f2tf32(float f) {
    uint32_t u;
    asm("cvt.rna.tf32.f32 %0, %1;" : "=r"(u) : "f"(f));
    return u;
}

#define MMA_TF32(acc, a, b) \
    asm volatile( \
        "mma.sync.aligned.m16n8k8.row.col.f32.tf32.tf32.f32 " \
        "{%0,%1,%2,%3}, {%4,%5,%6,%7}, {%8,%9}, {%0,%1,%2,%3};" \
        : "+f"((acc)[0]), "+f"((acc)[1]), "+f"((acc)[2]), "+f"((acc)[3]) \
        : "r"((a)[0]), "r"((a)[1]), "r"((a)[2]), "r"((a)[3]), \
          "r"((b)[0]), "r"((b)[1]))

// ===========================================================================
// Split-tf32 GEMM1 partial (fp32-equivalent accuracy), split-K over blockIdx.z.
// Cp[z][m,n] = sum_{k in slice z} A[m,k]*B[n,k]   (bias/tanh in reduce)
// BM=BN=64, BK=32, 128 threads, 2x2 warps, 32x32 warp tile.
// ===========================================================================
template<int K, int KS>     // KS = K per slice
__global__ void __launch_bounds__(128)
gemm_split_part(const float* __restrict__ A, const float* __restrict__ Bm,
                float* __restrict__ Cp)
{
    constexpr int PITCH = 68;            // hi at [0,32), lo at [32,64)
    constexpr int NKT   = KS / 32;

    __shared__ uint32_t As[64][PITCH];
    __shared__ uint32_t Bs[64][PITCH];

    const int tid  = threadIdx.x;
    const int lane = tid & 31;
    const int warp = tid >> 5;
    const int wm   = warp >> 1;
    const int wn   = warp & 1;
    const int gid  = lane >> 2;
    const int tig  = lane & 3;

    const int m0 = blockIdx.y * 64;
    const int n0 = blockIdx.x * 64;
    const int kbase = blockIdx.z * KS;
    float* __restrict__ C = Cp + (size_t)blockIdx.z * (BB * DD);

    const int lr = tid >> 3;
    const int lc = tid & 7;

    float c[2][4][4];
    #pragma unroll
    for (int i = 0; i < 2; i++)
        #pragma unroll
        for (int j = 0; j < 4; j++)
            #pragma unroll
            for (int q = 0; q < 4; q++) c[i][j][q] = 0.f;

    float4 pa[4], pb[4];

    auto load_tile = [&](int kk) {
        #pragma unroll
        for (int i = 0; i < 4; i++) {
            const int r = lr + i * 16;
            pa[i] = *(const float4*)(A  + (size_t)(m0 + r) * K + kk + lc * 4);
            pb[i] = *(const float4*)(Bm + (size_t)(n0 + r) * K + kk + lc * 4);
        }
    };
    auto store_tile = [&]() {
        #pragma unroll
        for (int i = 0; i < 4; i++) {
            const int r = lr + i * 16;
            uint4 ah = make_uint4(f2tf32(pa[i].x), f2tf32(pa[i].y),
                                  f2tf32(pa[i].z), f2tf32(pa[i].w));
            uint4 bh = make_uint4(f2tf32(pb[i].x), f2tf32(pb[i].y),
                                  f2tf32(pb[i].z), f2tf32(pb[i].w));
            uint4 al = make_uint4(f2tf32(pa[i].x - __uint_as_float(ah.x)),
                                  f2tf32(pa[i].y - __uint_as_float(ah.y)),
                                  f2tf32(pa[i].z - __uint_as_float(ah.z)),
                                  f2tf32(pa[i].w - __uint_as_float(ah.w)));
            uint4 bl = make_uint4(f2tf32(pb[i].x - __uint_as_float(bh.x)),
                                  f2tf32(pb[i].y - __uint_as_float(bh.y)),
                                  f2tf32(pb[i].z - __uint_as_float(bh.z)),
                                  f2tf32(pb[i].w - __uint_as_float(bh.w)));
            *(uint4*)&As[r][lc * 4]      = ah;
            *(uint4*)&As[r][32 + lc * 4] = al;
            *(uint4*)&Bs[r][lc * 4]      = bh;
            *(uint4*)&Bs[r][32 + lc * 4] = bl;
        }
    };

    load_tile(kbase);
    store_tile();
    __syncthreads();

    for (int kt = 0; kt < NKT; kt++) {
        if (kt + 1 < NKT) load_tile(kbase + (kt + 1) * 32);

        #pragma unroll
        for (int k8 = 0; k8 < 4; k8++) {
            const int k0 = k8 * 8;

            uint32_t af[2][4], afl[2][4];
            #pragma unroll
            for (int mi = 0; mi < 2; mi++) {
                const int row = wm * 32 + mi * 16 + gid;
                af[mi][0]  = As[row    ][k0 + tig];
                af[mi][1]  = As[row + 8][k0 + tig];
                af[mi][2]  = As[row    ][k0 + tig + 4];
                af[mi][3]  = As[row + 8][k0 + tig + 4];
                afl[mi][0] = As[row    ][32 + k0 + tig];
                afl[mi][1] = As[row + 8][32 + k0 + tig];
                afl[mi][2] = As[row    ][32 + k0 + tig + 4];
                afl[mi][3] = As[row + 8][32 + k0 + tig + 4];
            }
            uint32_t bf[4][2], bfl[4][2];
            #pragma unroll
            for (int nj = 0; nj < 4; nj++) {
                const int col = wn * 32 + nj * 8 + gid;
                bf[nj][0]  = Bs[col][k0 + tig];
                bf[nj][1]  = Bs[col][k0 + tig + 4];
                bfl[nj][0] = Bs[col][32 + k0 + tig];
                bfl[nj][1] = Bs[col][32 + k0 + tig + 4];
            }

            #pragma unroll
            for (int mi = 0; mi < 2; mi++)
                #pragma unroll
                for (int nj = 0; nj < 4; nj++) {
                    MMA_TF32(c[mi][nj], af[mi],  bf[nj]);    // hi*hi
                    MMA_TF32(c[mi][nj], af[mi],  bfl[nj]);   // hi*lo
                    MMA_TF32(c[mi][nj], afl[mi], bf[nj]);    // lo*hi
                }
        }

        if (kt + 1 < NKT) {
            __syncthreads();
            store_tile();
            __syncthreads();
        }
    }

    #pragma unroll
    for (int mi = 0; mi < 2; mi++) {
        const int row = m0 + wm * 32 + mi * 16 + gid;
        #pragma unroll
        for (int nj = 0; nj < 4; nj++) {
            const int col = n0 + wn * 32 + nj * 8 + tig * 2;
            *(float2*)(C + (size_t)row * DD + col) =
                make_float2(c[mi][nj][0], c[mi][nj][1]);
            *(float2*)(C + (size_t)(row + 8) * DD + col) =
                make_float2(c[mi][nj][2], c[mi][nj][3]);
        }
    }
}

// ===========================================================================
// GEMM2 partial: single-pass tf32, double-buffered, split-K over blockIdx.z.
// ===========================================================================
template<int K, int KS>
__global__ void __launch_bounds__(128)
gemm_db_part(const float* __restrict__ A, const float* __restrict__ Bm,
             float* __restrict__ Cp)
{
    constexpr int PITCH = 36;
    constexpr int NKT   = KS / 32;

    __shared__ uint32_t As[2][64][PITCH];
    __shared__ uint32_t Bs[2][64][PITCH];

    const int tid  = threadIdx.x;
    const int lane = tid & 31;
    const int warp = tid >> 5;
    const int wm   = warp >> 1;
    const int wn   = warp & 1;
    const int gid  = lane >> 2;
    const int tig  = lane & 3;

    const int m0 = blockIdx.y * 64;
    const int n0 = blockIdx.x * 64;
    const int kbase = blockIdx.z * KS;
    float* __restrict__ C = Cp + (size_t)blockIdx.z * (BB * DD);

    const int lr = tid >> 3;
    const int lc = tid & 7;

    float c[2][4][4];
    #pragma unroll
    for (int i = 0; i < 2; i++)
        #pragma unroll
        for (int j = 0; j < 4; j++)
            #pragma unroll
            for (int q = 0; q < 4; q++) c[i][j][q] = 0.f;

    float4 pa[4], pb[4];

    auto load_tile = [&](int kk) {
        #pragma unroll
        for (int i = 0; i < 4; i++) {
            const int r = lr + i * 16;
            pa[i] = *(const float4*)(A  + (size_t)(m0 + r) * K + kk + lc * 4);
            pb[i] = *(const float4*)(Bm + (size_t)(n0 + r) * K + kk + lc * 4);
        }
    };
    auto store_tile = [&](int buf) {
        #pragma unroll
        for (int i = 0; i < 4; i++) {
            const int r = lr + i * 16;
            *(uint4*)&As[buf][r][lc * 4] = make_uint4(f2tf32(pa[i].x), f2tf32(pa[i].y),
                                                      f2tf32(pa[i].z), f2tf32(pa[i].w));
            *(uint4*)&Bs[buf][r][lc * 4] = make_uint4(f2tf32(pb[i].x), f2tf32(pb[i].y),
                                                      f2tf32(pb[i].z), f2tf32(pb[i].w));
        }
    };

    load_tile(kbase);
    store_tile(0);
    __syncthreads();

    for (int kt = 0; kt < NKT; kt++) {
        const int buf = kt & 1;
        if (kt + 1 < NKT) load_tile(kbase + (kt + 1) * 32);

        #pragma unroll
        for (int k8 = 0; k8 < 4; k8++) {
            const int k0 = k8 * 8;

            uint32_t af[2][4];
            #pragma unroll
            for (int mi = 0; mi < 2; mi++) {
                const int row = wm * 32 + mi * 16 + gid;
                af[mi][0] = As[buf][row    ][k0 + tig];
                af[mi][1] = As[buf][row + 8][k0 + tig];
                af[mi][2] = As[buf][row    ][k0 + tig + 4];
                af[mi][3] = As[buf][row + 8][k0 + tig + 4];
            }
            uint32_t bf[4][2];
            #pragma unroll
            for (int nj = 0; nj < 4; nj++) {
                const int col = wn * 32 + nj * 8 + gid;
                bf[nj][0] = Bs[buf][col][k0 + tig];
                bf[nj][1] = Bs[buf][col][k0 + tig + 4];
            }

            #pragma unroll
            for (int mi = 0; mi < 2; mi++)
                #pragma unroll
                for (int nj = 0; nj < 4; nj++)
                    MMA_TF32(c[mi][nj], af[mi], bf[nj]);
        }

        if (kt + 1 < NKT) store_tile(buf ^ 1);
        __syncthreads();
    }

    #pragma unroll
    for (int mi = 0; mi < 2; mi++) {
        const int row = m0 + wm * 32 + mi * 16 + gid;
        #pragma unroll
        for (int nj = 0; nj < 4; nj++) {
            const int col = n0 + wn * 32 + nj * 8 + tig * 2;
            *(float2*)(C + (size_t)row * DD + col) =
                make_float2(c[mi][nj][0], c[mi][nj][1]);
            *(float2*)(C + (size_t)(row + 8) * DD + col) =
                make_float2(c[mi][nj][2], c[mi][nj][3]);
        }
    }
}

// ---------------------------------------------------------------------------
// Fused: t = tanh(p0+p1+bias); tn = t / max(||t||, 1e-12). One block per row.
// ---------------------------------------------------------------------------
__global__ void __launch_bounds__(256)
reduce_tanh_norm_kernel(const float* __restrict__ p0, const float* __restrict__ p1,
                        const float* __restrict__ bias, float* __restrict__ out)
{
    const int b = blockIdx.x;
    const int t = threadIdx.x;
    const int lane = t & 31, warp = t >> 5;

    float4 a  = ((const float4*)(p0 + (size_t)b * DD))[t];
    float4 a1 = ((const float4*)(p1 + (size_t)b * DD))[t];
    float4 bb = ((const float4*)bias)[t];
    float4 v;
    v.x = tanhf(a.x + a1.x + bb.x);
    v.y = tanhf(a.y + a1.y + bb.y);
    v.z = tanhf(a.z + a1.z + bb.z);
    v.w = tanhf(a.w + a1.w + bb.w);

    float ss = v.x*v.x + v.y*v.y + v.z*v.z + v.w*v.w;
    #pragma unroll
    for (int o = 16; o; o >>= 1) ss += __shfl_xor_sync(0xffffffffu, ss, o);

    __shared__ float sred[8];
    __shared__ float sinv;
    if (lane == 0) sred[warp] = ss;
    __syncthreads();
    if (t == 0) {
        float tot = 0.f;
        #pragma unroll
        for (int w = 0; w < 8; w++) tot += sred[w];
        sinv = 1.0f / fmaxf(sqrtf(tot), 1e-12f);
    }
    __syncthreads();
    const float inv = sinv;
    v.x *= inv; v.y *= inv; v.z *= inv; v.w *= inv;
    ((float4*)(out + (size_t)b * DD))[t] = v;
}

// ---------------------------------------------------------------------------
// out = p0 + p1 (vectorized, fixed order => deterministic)
// ---------------------------------------------------------------------------
__global__ void __launch_bounds__(256)
reduce_add_kernel(const float* __restrict__ p0, const float* __restrict__ p1,
                  float* __restrict__ out)
{
    const int i = blockIdx.x * 256 + threadIdx.x;
    float4 a = ((const float4*)p0)[i];
    float4 b = ((const float4*)p1)[i];
    ((float4*)out)[i] = make_float4(a.x + b.x, a.y + b.y, a.z + b.z, a.w + b.w);
}

// ---------------------------------------------------------------------------
// sims + argmax + gather (HBM-bound; reads 1 GB once)
// ---------------------------------------------------------------------------
__global__ void __launch_bounds__(256)
sims_argmax_kernel(const float* __restrict__ visual,
                   const float* __restrict__ tn,
                   float* __restrict__ vb)
{
    const int b = blockIdx.x;
    const int lane = threadIdx.x & 31;
    const int warp = threadIdx.x >> 5;

    const float4* v4 = (const float4*)(visual + (size_t)b * PP * DD);
    const float4* t4 = (const float4*)(tn + (size_t)b * DD);

    float4 tr[8];
    #pragma unroll
    for (int k = 0; k < 8; k++) tr[k] = t4[lane + 32 * k];

    float best = -1e30f; int bidx = 0; float bss = 1.f;

    #pragma unroll 2
    for (int pp = 0; pp < 32; pp++) {
        const int p = warp * 32 + pp;
        const float4* row = v4 + (size_t)p * (DD / 4);
        float dot = 0.f, ss = 0.f;
        #pragma unroll
        for (int k = 0; k < 8; k++) {
            float4 v = row[lane + 32 * k];
            dot += v.x * tr[k].x + v.y * tr[k].y + v.z * tr[k].z + v.w * tr[k].w;
            ss  += v.x * v.x + v.y * v.y + v.z * v.z + v.w * v.w;
        }
        #pragma unroll
        for (int o = 16; o; o >>= 1) {
            dot += __shfl_xor_sync(0xffffffffu, dot, o);
            ss  += __shfl_xor_sync(0xffffffffu, ss,  o);
        }
        const float sim = dot / fmaxf(sqrtf(ss), 1e-12f);
        if (sim > best) { best = sim; bidx = p; bss = ss; }
    }

    __shared__ float sval[8]; __shared__ int sidx[8]; __shared__ float ssum[8];
    __shared__ int s_p; __shared__ float s_inv;
    if (lane == 0) { sval[warp] = best; sidx[warp] = bidx; ssum[warp] = bss; }
    __syncthreads();
    if (threadIdx.x == 0) {
        float bv = sval[0]; int bi = sidx[0]; float bs = ssum[0];
        #pragma unroll
        for (int w = 1; w < 8; w++) {
            if (sval[w] > bv || (sval[w] == bv && sidx[w] < bi)) {
                bv = sval[w]; bi = sidx[w]; bs = ssum[w];
            }
        }
        s_p = bi;
        s_inv = 1.0f / fmaxf(sqrtf(bs), 1e-12f);
    }
    __syncthreads();

    const int p = s_p;
    const float inv = s_inv;
    const float4* row = v4 + (size_t)p * (DD / 4);
    float4* ob = (float4*)(vb + (size_t)b * DD);
    for (int i = threadIdx.x; i < DD / 4; i += 256) {
        float4 v = row[i];
        v.x *= inv; v.y *= inv; v.z *= inv; v.w *= inv;
        ob[i] = v;
    }
}

// ---------------------------------------------------------------------------
extern "C" void kernel_launch(void* const* d_in, const int* in_sizes, int n_in,
                              void* d_out, int out_size)
{
    const float* visual = (const float*)d_in[0];   // [1024, 256, 1024]
    const float* text   = (const float*)d_in[1];   // [1024, 512]
    const float* W      = (const float*)d_in[2];   // [1024, 512]
    const float* bias   = (const float*)d_in[3];   // [1024]
    float* out = (float*)d_out;                    // [1024, 1024]

    float *p_tn, *p_vb, *p_part;
    cudaGetSymbolAddress((void**)&p_tn,   g_tn);
    cudaGetSymbolAddress((void**)&p_vb,   g_vb);
    cudaGetSymbolAddress((void**)&p_part, g_part);

    // 1) partials of text @ W^T  (split-tf32, split-K=2)
    gemm_split_part<DC, DC/2><<<dim3(16, 16, 2), 128>>>(text, W, p_part);
    // 2) tn = l2norm(tanh(p0+p1+bias))   (fused reduce)
    reduce_tanh_norm_kernel<<<BB, 256>>>(p_part, p_part + BB * DD, bias, p_tn);
    // 3) per-b argmax over patches + gather normalized best patch
    sims_argmax_kernel<<<BB, 256>>>(visual, p_tn, p_vb);
    // 4) partials of tn @ vb^T  (single-pass tf32, split-K=2)
    gemm_db_part<DD, DD/2><<<dim3(16, 16, 2), 128>>>(p_tn, p_vb, p_part);
    // 5) out = p0 + p1
    reduce_add_kernel<<<BB * DD / 4 / 256, 256>>>(p_part, p_part + BB * DD, out);
}